// round 16
// baseline (speedup 1.0000x reference)
#include <cuda_runtime.h>
#include <cuda_fp16.h>
#include <cstdint>
#include <math.h>

#define BATCH 32
#define LQ    1024
#define LK    1024
#define HID   1024
#define KDIM  1024

// ---------------------------------------------------------------------------
// Device scratch (BSS). +128 pad rows where GEMM tile tails can read past the
// live region (all-selected corner case).
// ---------------------------------------------------------------------------
#define QN   ((size_t)BATCH * LQ * KDIM)
#define QNP  (QN + (size_t)128 * KDIM)
#define WN   ((size_t)HID * KDIM)
__device__ __half g_qh[QNP],  g_ql[QNP];
__device__ __half g_kh[QNP],  g_kl[QNP];
__device__ __half g_wqh[WN],  g_wql[WN];
__device__ __half g_wkh[WN],  g_wkl[WN];
__device__ __half g_qph[QNP], g_qpl[QNP];
__device__ __half g_kph[QNP], g_kpl[QNP];
__device__ float  g_logc[QN];
__device__ int    g_qidx[BATCH * LQ];
__device__ int    g_kidx[BATCH * LK];
__device__ int    g_qcnt[BATCH];
__device__ int    g_kcnt[BATCH];
__device__ int    g_qoff[BATCH + 1];
__device__ int    g_koff[BATCH + 1];

// ---------------------------------------------------------------------------
// PTX helpers (portable compute_103 ISA)
// ---------------------------------------------------------------------------
__device__ __forceinline__ uint32_t smem_u32(const void* p) {
    uint32_t a;
    asm("{ .reg .u64 t; cvta.to.shared.u64 t, %1; cvt.u32.u64 %0, t; }"
        : "=r"(a) : "l"(p));
    return a;
}

#define CP16(smem, gmem) \
    asm volatile("cp.async.cg.shared.global [%0], [%1], 16;" \
                 :: "r"(smem), "l"(gmem))
#define CP_COMMIT() asm volatile("cp.async.commit_group;" ::: "memory")
#define CP_WAIT2()  asm volatile("cp.async.wait_group 2;" ::: "memory")

#define LDSM4(r, addr) \
    asm volatile("ldmatrix.sync.aligned.m8n8.x4.shared.b16 {%0,%1,%2,%3}, [%4];" \
        : "=r"((r)[0]), "=r"((r)[1]), "=r"((r)[2]), "=r"((r)[3]) : "r"(addr))

#define MMA16816(d, a, b0, b1) \
    asm volatile("mma.sync.aligned.m16n8k16.row.col.f32.f16.f16.f32 " \
        "{%0,%1,%2,%3}, {%4,%5,%6,%7}, {%8,%9}, {%0,%1,%2,%3};" \
        : "+f"((d)[0]), "+f"((d)[1]), "+f"((d)[2]), "+f"((d)[3]) \
        : "r"((a)[0]), "r"((a)[1]), "r"((a)[2]), "r"((a)[3]), \
          "r"(b0), "r"(b1))

#define MMA16816F16(d, a, b0, b1) \
    asm volatile("mma.sync.aligned.m16n8k16.row.col.f16.f16.f16.f16 " \
        "{%0,%1}, {%2,%3,%4,%5}, {%6,%7}, {%0,%1};" \
        : "+r"((d)[0]), "+r"((d)[1]) \
        : "r"((a)[0]), "r"((a)[1]), "r"((a)[2]), "r"((a)[3]), \
          "r"(b0), "r"(b1))

// ---------------------------------------------------------------------------
// Ballot-based mask partition per batch: warp popc prefix + 1 warp-sum scan.
// ---------------------------------------------------------------------------
__global__ void __launch_bounds__(1024) mask_scan_kernel(
    const int* __restrict__ qmask, const int* __restrict__ kmask,
    int* __restrict__ qidx, int* __restrict__ kidx,
    int* __restrict__ qcnt, int* __restrict__ kcnt)
{
    const int b = blockIdx.x;
    const int t = threadIdx.x;
    const int lane = t & 31;
    const int w = t >> 5;
    __shared__ int wsum[32];

#pragma unroll 1
    for (int pass = 0; pass < 2; pass++) {
        const int* mask = pass == 0 ? qmask : kmask;
        int*       idx  = pass == 0 ? qidx  : kidx;
        int*       cnt  = pass == 0 ? qcnt  : kcnt;
        const int m = mask[b * 1024 + t] != 0 ? 1 : 0;

        const unsigned bal = __ballot_sync(0xFFFFFFFFu, m);
        const int pre = __popc(bal & ((1u << lane) - 1u));   // excl. in-warp
        if (lane == 0) wsum[w] = __popc(bal);
        __syncthreads();
        if (w == 0) {
            int v = wsum[lane];
#pragma unroll
            for (int o = 1; o < 32; o <<= 1) {
                int u = __shfl_up_sync(0xFFFFFFFFu, v, o);
                if (lane >= o) v += u;
            }
            wsum[lane] = v;   // inclusive warp-sum scan
        }
        __syncthreads();
        const int base  = (w == 0) ? 0 : wsum[w - 1];
        const int total = wsum[31];
        const int rank  = base + pre;   // exclusive prefix of ones at t
        if (m) idx[b * 1024 + rank] = t;
        else   idx[b * 1024 + total + (t - rank)] = t;
        if (t == 0) cnt[b] = total;
        __syncthreads();
    }
}

__global__ void offsets_kernel(const int* __restrict__ qcnt,
                               const int* __restrict__ kcnt,
                               int* __restrict__ qoff, int* __restrict__ koff)
{
    if (threadIdx.x == 0) {
        int s = 0;
        for (int b = 0; b < BATCH; b++) { qoff[b] = s; s += qcnt[b]; }
        qoff[BATCH] = s;
    }
    if (threadIdx.x == 1) {
        int s = 0;
        for (int b = 0; b < BATCH; b++) { koff[b] = s; s += kcnt[b]; }
        koff[BATCH] = s;
    }
}

// ---------------------------------------------------------------------------
// Unified split launch, grid (1024, 32, 3):
//  z=0: query gather-split (selected rows, globally compacted)
//  z=1: key gather-split
//  z=2: weight split (y==0 -> Wq, y==1 -> Wk; block x covers 256 float4s)
// ---------------------------------------------------------------------------
__global__ void __launch_bounds__(256) split_all_kernel(
    const float* __restrict__ q,  const int* __restrict__ qidx,
    const int* __restrict__ qcnt, const int* __restrict__ qoff,
    __half* __restrict__ qho, __half* __restrict__ qlo,
    const float* __restrict__ k,  const int* __restrict__ kidx,
    const int* __restrict__ kcnt, const int* __restrict__ koff,
    __half* __restrict__ kho, __half* __restrict__ klo,
    const float* __restrict__ Wq, __half* __restrict__ wqh, __half* __restrict__ wql,
    const float* __restrict__ Wk, __half* __restrict__ wkh, __half* __restrict__ wkl)
{
    const int z = blockIdx.z;
    const int t = threadIdx.x;

    const float* srcp;
    __half *hp_, *lp_;
    long doff4;   // destination offset in float4 units

    if (z == 2) {
        const int b = blockIdx.y;
        if (b >= 2) return;
        const long lin = (long)blockIdx.x * 256 + t;   // < WN/4 = 262144
        srcp = (b == 0 ? Wq : Wk) + lin * 4;
        hp_  = (b == 0 ? wqh : wkh);
        lp_  = (b == 0 ? wql : wkl);
        doff4 = lin;
    } else {
        const int b = blockIdx.y;
        const int i = blockIdx.x;
        const int* cnt = z ? kcnt : qcnt;
        if (i >= cnt[b]) return;
        const int* idx = z ? kidx : qidx;
        const int* off = z ? koff : qoff;
        const float* x = z ? k : q;
        const int src = idx[b * 1024 + i];
        srcp = x + ((long)b * 1024 + src) * 1024 + (size_t)t * 4;
        hp_ = z ? kho : qho;
        lp_ = z ? klo : qlo;
        doff4 = (long)(off[b] + i) * 256 + t;
    }

    float4 v = *(const float4*)srcp;
    __half h0 = __float2half(v.x);
    __half h1 = __float2half(v.y);
    __half h2 = __float2half(v.z);
    __half h3 = __float2half(v.w);
    __half l0 = __float2half(v.x - __half2float(h0));
    __half l1 = __float2half(v.y - __half2float(h1));
    __half l2 = __float2half(v.z - __half2float(h2));
    __half l3 = __float2half(v.w - __half2float(h3));
    __half2* hp = (__half2*)(hp_ + doff4 * 4);
    __half2* lp = (__half2*)(lp_ + doff4 * 4);
    hp[0] = __halves2half2(h0, h1);
    hp[1] = __halves2half2(h2, h3);
    lp[0] = __halves2half2(l0, l1);
    lp[1] = __halves2half2(l2, l3);
}

// ---------------------------------------------------------------------------
// fp16x3 NT GEMM (round-14 champion, unchanged).
// ---------------------------------------------------------------------------
#define STG_BYTES 40960u
#define SMEM_BYTES (4u * STG_BYTES)

template <int EPI>
__global__ void __launch_bounds__(512, 1) gemm_fp16x3_kernel(
    const __half* __restrict__ Ah, const __half* __restrict__ Al,
    const __half* __restrict__ Bh, const __half* __restrict__ Bl,
    const float* __restrict__ bias,
    float* __restrict__ Cf,
    __half* __restrict__ Ch, __half* __restrict__ Cl,
    int K, int N, long sCz,
    const int* __restrict__ aOff, const int* __restrict__ aCnt,
    const int* __restrict__ bOff, const int* __restrict__ bCnt)
{
    extern __shared__ char smraw[];
    const uint32_t sb = smem_u32(smraw);
    const int tid = threadIdx.x;
    const int wid = tid >> 5;
    const int l   = tid & 31;

    const int bz = blockIdx.z;
    const long m0 = (long)blockIdx.y * 128;
    const long n0 = (long)blockIdx.x * 128;

    if (aCnt && m0 >= aCnt[bz]) return;
    if (bCnt && n0 >= bCnt[bz]) return;
    const long abase = aOff ? aOff[bz] : 0;
    const long bbase = bOff ? bOff[bz] : 0;
    if (EPI == 0) Cf += (long)bz * sCz;

    const int lr = tid >> 2;
    const int lc = tid & 3;
    const uint32_t srow = (uint32_t)(lr * 80 + lc * 16);
    const __half* gAh = Ah + (abase + m0 + lr) * (long)K + lc * 8;
    const __half* gAl = Al + (abase + m0 + lr) * (long)K + lc * 8;
    const __half* gBh = Bh + (bbase + n0 + lr) * (long)K + lc * 8;
    const __half* gBl = Bl + (bbase + n0 + lr) * (long)K + lc * 8;

    const int warpM = (wid >> 2) * 32;
    const int warpN = (wid & 3) * 32;
    const uint32_t aoff = (uint32_t)((warpM + (l & 15)) * 80 + (l >> 4) * 16);
    const uint32_t boff = (uint32_t)((warpN + (l & 7) + ((l >> 4) << 3)) * 80 +
                                     (((l >> 3) & 1) ? 16 : 0));

    auto load_stage = [&](int stage, int k0) {
        const uint32_t s = sb + (uint32_t)stage * STG_BYTES + srow;
        CP16(s,         gAh + k0);
        CP16(s + 10240, gAl + k0);
        CP16(s + 20480, gBh + k0);
        CP16(s + 30720, gBl + k0);
    };

    float acc[2][4][4];
    uint32_t accx[2][4][2];
#pragma unroll
    for (int i = 0; i < 2; i++)
#pragma unroll
        for (int j = 0; j < 4; j++) {
#pragma unroll
            for (int r = 0; r < 4; r++) acc[i][j][r] = 0.0f;
            accx[i][j][0] = 0u;
            accx[i][j][1] = 0u;
        }

    const int NK = K >> 5;

    load_stage(0, 0);  CP_COMMIT();
    load_stage(1, 32); CP_COMMIT();
    load_stage(2, 64); CP_COMMIT();

    for (int t = 0; t < NK; t++) {
        CP_WAIT2();
        __syncthreads();

        const int tn3 = t + 3;
        if (tn3 < NK) load_stage(tn3 & 3, tn3 * 32);
        CP_COMMIT();

        const uint32_t sbase = sb + (uint32_t)(t & 3) * STG_BYTES;
#pragma unroll
        for (int ks = 0; ks < 2; ks++) {
            uint32_t ah[2][4], al[2][4], bh[2][4], bl[2][4];
#pragma unroll
            for (int mt = 0; mt < 2; mt++)
                LDSM4(ah[mt], sbase + aoff + mt * 1280 + ks * 32);
#pragma unroll
            for (int np = 0; np < 2; np++)
                LDSM4(bh[np], sbase + 20480 + boff + np * 1280 + ks * 32);
#pragma unroll
            for (int mt = 0; mt < 2; mt++)
#pragma unroll
                for (int nt = 0; nt < 4; nt++)
                    MMA16816(acc[mt][nt], ah[mt],
                             bh[nt >> 1][(nt & 1) * 2], bh[nt >> 1][(nt & 1) * 2 + 1]);
#pragma unroll
            for (int mt = 0; mt < 2; mt++)
                LDSM4(al[mt], sbase + 10240 + aoff + mt * 1280 + ks * 32);
#pragma unroll
            for (int np = 0; np < 2; np++)
                LDSM4(bl[np], sbase + 30720 + boff + np * 1280 + ks * 32);
#pragma unroll
            for (int mt = 0; mt < 2; mt++)
#pragma unroll
                for (int nt = 0; nt < 4; nt++)
                    MMA16816F16(accx[mt][nt], ah[mt],
                                bl[nt >> 1][(nt & 1) * 2], bl[nt >> 1][(nt & 1) * 2 + 1]);
#pragma unroll
            for (int mt = 0; mt < 2; mt++)
#pragma unroll
                for (int nt = 0; nt < 4; nt++)
                    MMA16816F16(accx[mt][nt], al[mt],
                                bh[nt >> 1][(nt & 1) * 2], bh[nt >> 1][(nt & 1) * 2 + 1]);
        }
    }

    const int tm = l >> 2;
    const int tn = (l & 3) * 2;
#pragma unroll
    for (int mt = 0; mt < 2; mt++) {
        const long r0 = m0 + warpM + mt * 16 + tm;
        const long r1 = r0 + 8;
#pragma unroll
        for (int nt = 0; nt < 4; nt++) {
            const long col = n0 + warpN + nt * 8 + tn;
            float2 x01 = __half22float2(*(__half2*)&accx[mt][nt][0]);
            float2 x23 = __half22float2(*(__half2*)&accx[mt][nt][1]);
            float c0 = acc[mt][nt][0] + x01.x;
            float c1 = acc[mt][nt][1] + x01.y;
            float c2 = acc[mt][nt][2] + x23.x;
            float c3 = acc[mt][nt][3] + x23.y;
            if (EPI == 0) {
                *(float2*)(Cf + r0 * (long)N + col) = make_float2(c0, c1);
                *(float2*)(Cf + r1 * (long)N + col) = make_float2(c2, c3);
            } else {
                const float b0 = bias[col], b1 = bias[col + 1];
                float v0 = fmaxf(c0 + b0, 0.0f);
                float v1 = fmaxf(c1 + b1, 0.0f);
                float v2 = fmaxf(c2 + b0, 0.0f);
                float v3 = fmaxf(c3 + b1, 0.0f);
                __half h0 = __float2half(v0), h1 = __float2half(v1);
                __half h2 = __float2half(v2), h3 = __float2half(v3);
                __half e0 = __float2half(v0 - __half2float(h0));
                __half e1 = __float2half(v1 - __half2float(h1));
                __half e2 = __float2half(v2 - __half2float(h2));
                __half e3 = __float2half(v3 - __half2float(h3));
                *(__half2*)(Ch + r0 * (long)N + col) = __halves2half2(h0, h1);
                *(__half2*)(Ch + r1 * (long)N + col) = __halves2half2(h2, h3);
                *(__half2*)(Cl + r0 * (long)N + col) = __halves2half2(e0, e1);
                *(__half2*)(Cl + r1 * (long)N + col) = __halves2half2(e2, e3);
            }
        }
    }
}

// ---------------------------------------------------------------------------
// Softmax over compacted cols + scatter to full output (exact vs reference).
// ---------------------------------------------------------------------------
__global__ void __launch_bounds__(256) softmax_scatter_kernel(
    const float* __restrict__ logc,
    const int* __restrict__ qidx, const int* __restrict__ kidx,
    const int* __restrict__ qcnt, const int* __restrict__ kcnt,
    float* __restrict__ out)
{
    const int b = blockIdx.y;
    const int i = blockIdx.x;
    const int tid = threadIdx.x;
    const int qc = qcnt[b];
    const int orow = qidx[b * 1024 + i];
    float* dst = out + ((long)b * 1024 + orow) * 1024;

    if (i >= qc) {
        ((float4*)dst)[tid] = make_float4(0.f, 0.f, 0.f, 0.f);
        return;
    }

    const int kc = kcnt[b];
    const float* src = logc + ((long)b * 1024 + i) * 1024;
    const int j0 = tid * 4;

    __shared__ float row[1024];
    __shared__ float red[8];

    float4 v = ((const float4*)src)[tid];
    float x0 = (j0 + 0 < kc) ? v.x : -1e30f;
    float x1 = (j0 + 1 < kc) ? v.y : -1e30f;
    float x2 = (j0 + 2 < kc) ? v.z : -1e30f;
    float x3 = (j0 + 3 < kc) ? v.w : -1e30f;

    float mx = fmaxf(fmaxf(x0, x1), fmaxf(x2, x3));
#pragma unroll
    for (int o = 16; o > 0; o >>= 1)
        mx = fmaxf(mx, __shfl_xor_sync(0xFFFFFFFFu, mx, o));
    if ((tid & 31) == 0) red[tid >> 5] = mx;
    __syncthreads();
    float bmx = red[0];
#pragma unroll
    for (int w = 1; w < 8; w++) bmx = fmaxf(bmx, red[w]);
    __syncthreads();

    float e0 = expf(x0 - bmx);
    float e1 = expf(x1 - bmx);
    float e2 = expf(x2 - bmx);
    float e3 = expf(x3 - bmx);
    float s = e0 + e1 + e2 + e3;
#pragma unroll
    for (int o = 16; o > 0; o >>= 1)
        s += __shfl_xor_sync(0xFFFFFFFFu, s, o);
    if ((tid & 31) == 0) red[tid >> 5] = s;
    __syncthreads();
    float bs = 0.0f;
#pragma unroll
    for (int w = 0; w < 8; w++) bs += red[w];
    const float inv = 1.0f / bs;

    ((float4*)row)[tid] = make_float4(0.f, 0.f, 0.f, 0.f);
    __syncthreads();
    const int* kix = kidx + b * 1024;
    if (j0 + 0 < kc) row[kix[j0 + 0]] = e0 * inv;
    if (j0 + 1 < kc) row[kix[j0 + 1]] = e1 * inv;
    if (j0 + 2 < kc) row[kix[j0 + 2]] = e2 * inv;
    if (j0 + 3 < kc) row[kix[j0 + 3]] = e3 * inv;
    __syncthreads();

    ((float4*)dst)[tid] = ((float4*)row)[tid];
}

// ---------------------------------------------------------------------------
// kernel_launch
// ---------------------------------------------------------------------------
extern "C" void kernel_launch(void* const* d_in, const int* in_sizes, int n_in,
                              void* d_out, int out_size)
{
    const float* query = (const float*)d_in[0];
    const float* key   = (const float*)d_in[1];
    const int*   qmask = (const int*)  d_in[2];
    const int*   kmask = (const int*)  d_in[3];
    const float* Wq    = (const float*)d_in[4];
    const float* bq    = (const float*)d_in[5];
    const float* Wk    = (const float*)d_in[6];
    const float* bk    = (const float*)d_in[7];
    float* out = (float*)d_out;

    __half *qh, *ql, *kh, *kl, *wqh, *wql, *wkh, *wkl;
    __half *qph, *qpl, *kph, *kpl;
    float* logc;
    int *qidx, *kidx, *qcnt, *kcnt, *qoff, *koff;
    cudaGetSymbolAddress((void**)&qh,   g_qh);
    cudaGetSymbolAddress((void**)&ql,   g_ql);
    cudaGetSymbolAddress((void**)&kh,   g_kh);
    cudaGetSymbolAddress((void**)&kl,   g_kl);
    cudaGetSymbolAddress((void**)&wqh,  g_wqh);
    cudaGetSymbolAddress((void**)&wql,  g_wql);
    cudaGetSymbolAddress((void**)&wkh,  g_wkh);
    cudaGetSymbolAddress((void**)&wkl,  g_wkl);
    cudaGetSymbolAddress((void**)&qph,  g_qph);
    cudaGetSymbolAddress((void**)&qpl,  g_qpl);
    cudaGetSymbolAddress((void**)&kph,  g_kph);
    cudaGetSymbolAddress((void**)&kpl,  g_kpl);
    cudaGetSymbolAddress((void**)&logc, g_logc);
    cudaGetSymbolAddress((void**)&qidx, g_qidx);
    cudaGetSymbolAddress((void**)&kidx, g_kidx);
    cudaGetSymbolAddress((void**)&qcnt, g_qcnt);
    cudaGetSymbolAddress((void**)&kcnt, g_kcnt);
    cudaGetSymbolAddress((void**)&qoff, g_qoff);
    cudaGetSymbolAddress((void**)&koff, g_koff);

    cudaFuncSetAttribute(gemm_fp16x3_kernel<0>,
                         cudaFuncAttributeMaxDynamicSharedMemorySize, SMEM_BYTES);
    cudaFuncSetAttribute(gemm_fp16x3_kernel<1>,
                         cudaFuncAttributeMaxDynamicSharedMemorySize, SMEM_BYTES);

    // Mask partition (ballot scan) + global offsets
    mask_scan_kernel<<<BATCH, 1024>>>(qmask, kmask, qidx, kidx, qcnt, kcnt);
    offsets_kernel<<<1, 32>>>(qcnt, kcnt, qoff, koff);

    // Unified split: q gather (z=0), k gather (z=1), weights (z=2)
    dim3 gsp(LQ, BATCH, 3);
    split_all_kernel<<<gsp, 256>>>(
        query, qidx, qcnt, qoff, qh, ql,
        key,   kidx, kcnt, koff, kh, kl,
        Wq, wqh, wql, Wk, wkh, wkl);

    // Projections over globally-compacted rows (two lean launches, as r14)
    dim3 gproj(HID / 128, (BATCH * LQ) / 128, 1);   // (8, 256, 1)
    gemm_fp16x3_kernel<1><<<gproj, 512, SMEM_BYTES>>>(
        qh, ql, wqh, wql, bq, nullptr, qph, qpl,
        KDIM, HID, 0, nullptr, qoff + BATCH, nullptr, nullptr);
    gemm_fp16x3_kernel<1><<<gproj, 512, SMEM_BYTES>>>(
        kh, kl, wkh, wkl, bk, nullptr, kph, kpl,
        KDIM, HID, 0, nullptr, koff + BATCH, nullptr, nullptr);

    // Batched compacted logits
    dim3 glog(LK / 128, LQ / 128, BATCH);
    gemm_fp16x3_kernel<0><<<glog, 512, SMEM_BYTES>>>(
        qph, qpl, kph, kpl, nullptr, logc, nullptr, nullptr,
        HID, LK, (long)LQ * LK, qoff, qcnt, koff, kcnt);

    // Softmax + scatter
    dim3 gsm(LQ, BATCH);
    softmax_scatter_kernel<<<gsm, 256>>>(logc, qidx, kidx, qcnt, kcnt, out);
}

// round 17
// speedup vs baseline: 1.0172x; 1.0172x over previous
#include <cuda_runtime.h>
#include <cuda_fp16.h>
#include <cstdint>
#include <math.h>

#define BATCH 32
#define LQ    1024
#define LK    1024
#define HID   1024
#define KDIM  1024

// ---------------------------------------------------------------------------
// Device scratch (BSS). +128 pad rows where GEMM tile tails can read past the
// live region (all-selected corner case).
// ---------------------------------------------------------------------------
#define QN   ((size_t)BATCH * LQ * KDIM)
#define QNP  (QN + (size_t)128 * KDIM)
#define WN   ((size_t)HID * KDIM)
__device__ __half g_qh[QNP],  g_ql[QNP];
__device__ __half g_kh[QNP],  g_kl[QNP];
__device__ __half g_wqh[WN],  g_wql[WN];
__device__ __half g_wkh[WN],  g_wkl[WN];
__device__ __half g_qph[QNP], g_qpl[QNP];
__device__ __half g_kph[QNP], g_kpl[QNP];
__device__ float  g_logc[QN];
__device__ int    g_qidx[BATCH * LQ];
__device__ int    g_kidx[BATCH * LK];
__device__ int    g_qcnt[BATCH];
__device__ int    g_kcnt[BATCH];
__device__ int    g_qoff[BATCH + 1];
__device__ int    g_koff[BATCH + 1];

// ---------------------------------------------------------------------------
// PTX helpers (portable compute_103 ISA)
// ---------------------------------------------------------------------------
__device__ __forceinline__ uint32_t smem_u32(const void* p) {
    uint32_t a;
    asm("{ .reg .u64 t; cvta.to.shared.u64 t, %1; cvt.u32.u64 %0, t; }"
        : "=r"(a) : "l"(p));
    return a;
}

#define CP16(smem, gmem) \
    asm volatile("cp.async.cg.shared.global [%0], [%1], 16;" \
                 :: "r"(smem), "l"(gmem))
#define CP_COMMIT() asm volatile("cp.async.commit_group;" ::: "memory")
#define CP_WAIT2()  asm volatile("cp.async.wait_group 2;" ::: "memory")

#define LDSM4(r, addr) \
    asm volatile("ldmatrix.sync.aligned.m8n8.x4.shared.b16 {%0,%1,%2,%3}, [%4];" \
        : "=r"((r)[0]), "=r"((r)[1]), "=r"((r)[2]), "=r"((r)[3]) : "r"(addr))

#define MMA16816(d, a, b0, b1) \
    asm volatile("mma.sync.aligned.m16n8k16.row.col.f32.f16.f16.f32 " \
        "{%0,%1,%2,%3}, {%4,%5,%6,%7}, {%8,%9}, {%0,%1,%2,%3};" \
        : "+f"((d)[0]), "+f"((d)[1]), "+f"((d)[2]), "+f"((d)[3]) \
        : "r"((a)[0]), "r"((a)[1]), "r"((a)[2]), "r"((a)[3]), \
          "r"(b0), "r"(b1))

#define MMA16816F16(d, a, b0, b1) \
    asm volatile("mma.sync.aligned.m16n8k16.row.col.f16.f16.f16.f16 " \
        "{%0,%1}, {%2,%3,%4,%5}, {%6,%7}, {%0,%1};" \
        : "+r"((d)[0]), "+r"((d)[1]) \
        : "r"((a)[0]), "r"((a)[1]), "r"((a)[2]), "r"((a)[3]), \
          "r"(b0), "r"(b1))

// ---------------------------------------------------------------------------
// Ballot-based mask partition per batch (2 barriers; verified bit-identical
// output to the Hillis-Steele version in round 16).
// ---------------------------------------------------------------------------
__global__ void __launch_bounds__(1024) mask_scan_kernel(
    const int* __restrict__ qmask, const int* __restrict__ kmask,
    int* __restrict__ qidx, int* __restrict__ kidx,
    int* __restrict__ qcnt, int* __restrict__ kcnt)
{
    const int b = blockIdx.x;
    const int t = threadIdx.x;
    const int lane = t & 31;
    const int w = t >> 5;
    __shared__ int wsum[32];

#pragma unroll 1
    for (int pass = 0; pass < 2; pass++) {
        const int* mask = pass == 0 ? qmask : kmask;
        int*       idx  = pass == 0 ? qidx  : kidx;
        int*       cnt  = pass == 0 ? qcnt  : kcnt;
        const int m = mask[b * 1024 + t] != 0 ? 1 : 0;

        const unsigned bal = __ballot_sync(0xFFFFFFFFu, m);
        const int pre = __popc(bal & ((1u << lane) - 1u));
        if (lane == 0) wsum[w] = __popc(bal);
        __syncthreads();
        if (w == 0) {
            int v = wsum[lane];
#pragma unroll
            for (int o = 1; o < 32; o <<= 1) {
                int u = __shfl_up_sync(0xFFFFFFFFu, v, o);
                if (lane >= o) v += u;
            }
            wsum[lane] = v;
        }
        __syncthreads();
        const int base  = (w == 0) ? 0 : wsum[w - 1];
        const int total = wsum[31];
        const int rank  = base + pre;
        if (m) idx[b * 1024 + rank] = t;
        else   idx[b * 1024 + total + (t - rank)] = t;
        if (t == 0) cnt[b] = total;
        __syncthreads();
    }
}

__global__ void offsets_kernel(const int* __restrict__ qcnt,
                               const int* __restrict__ kcnt,
                               int* __restrict__ qoff, int* __restrict__ koff)
{
    if (threadIdx.x == 0) {
        int s = 0;
        for (int b = 0; b < BATCH; b++) { qoff[b] = s; s += qcnt[b]; }
        qoff[BATCH] = s;
    }
    if (threadIdx.x == 1) {
        int s = 0;
        for (int b = 0; b < BATCH; b++) { koff[b] = s; s += kcnt[b]; }
        koff[BATCH] = s;
    }
}

// ---------------------------------------------------------------------------
// Gather-split: convert ONLY selected rows fp32 -> (hi,lo) fp16, writing them
// globally compacted (row off[b]+i). Block = one candidate row.
// ---------------------------------------------------------------------------
__global__ void __launch_bounds__(256) split_gather_kernel(
    const float* __restrict__ x, const int* __restrict__ idx,
    const int* __restrict__ cnt, const int* __restrict__ off,
    __half* __restrict__ h, __half* __restrict__ l)
{
    const int b = blockIdx.y;
    const int i = blockIdx.x;
    if (i >= cnt[b]) return;
    const int t = threadIdx.x;
    const int src = idx[b * 1024 + i];
    const float* srow = x + ((long)b * 1024 + src) * 1024;
    const long drow = (long)(off[b] + i) * 1024;

    float4 v = ((const float4*)srow)[t];
    __half h0 = __float2half(v.x);
    __half h1 = __float2half(v.y);
    __half h2 = __float2half(v.z);
    __half h3 = __float2half(v.w);
    __half l0 = __float2half(v.x - __half2float(h0));
    __half l1 = __float2half(v.y - __half2float(h1));
    __half l2 = __float2half(v.z - __half2float(h2));
    __half l3 = __float2half(v.w - __half2float(h3));
    __half2* hp = (__half2*)(h + drow + (size_t)t * 4);
    __half2* lp = (__half2*)(l + drow + (size_t)t * 4);
    hp[0] = __halves2half2(h0, h1);
    hp[1] = __halves2half2(h2, h3);
    lp[0] = __halves2half2(l0, l1);
    lp[1] = __halves2half2(l2, l3);
}

// Plain split for the weights (full tensors, small).
__global__ void __launch_bounds__(256) split_kernel(
    const float* __restrict__ x0, __half* __restrict__ h0o, __half* __restrict__ l0o,
    const float* __restrict__ x1, __half* __restrict__ h1o, __half* __restrict__ l1o,
    int n4)
{
    const float* x = (blockIdx.y == 0) ? x0 : x1;
    __half* h = (blockIdx.y == 0) ? h0o : h1o;
    __half* l = (blockIdx.y == 0) ? l0o : l1o;
    int i = blockIdx.x * 256 + threadIdx.x;
    if (i >= n4) return;
    float4 v = ((const float4*)x)[i];
    __half h0 = __float2half(v.x);
    __half h1 = __float2half(v.y);
    __half h2 = __float2half(v.z);
    __half h3 = __float2half(v.w);
    __half l0 = __float2half(v.x - __half2float(h0));
    __half l1 = __float2half(v.y - __half2float(h1));
    __half l2 = __float2half(v.z - __half2float(h2));
    __half l3 = __float2half(v.w - __half2float(h3));
    __half2* hp = (__half2*)(h + (size_t)i * 4);
    __half2* lp = (__half2*)(l + (size_t)i * 4);
    hp[0] = __halves2half2(h0, h1);
    hp[1] = __halves2half2(h2, h3);
    lp[0] = __halves2half2(l0, l1);
    lp[1] = __halves2half2(l2, l3);
}

// ---------------------------------------------------------------------------
// fp16x3 NT GEMM (round-14 champion, unchanged).
// ---------------------------------------------------------------------------
#define STG_BYTES 40960u
#define SMEM_BYTES (4u * STG_BYTES)

template <int EPI>
__global__ void __launch_bounds__(512, 1) gemm_fp16x3_kernel(
    const __half* __restrict__ Ah, const __half* __restrict__ Al,
    const __half* __restrict__ Bh, const __half* __restrict__ Bl,
    const float* __restrict__ bias,
    float* __restrict__ Cf,
    __half* __restrict__ Ch, __half* __restrict__ Cl,
    int K, int N, long sCz,
    const int* __restrict__ aOff, const int* __restrict__ aCnt,
    const int* __restrict__ bOff, const int* __restrict__ bCnt)
{
    extern __shared__ char smraw[];
    const uint32_t sb = smem_u32(smraw);
    const int tid = threadIdx.x;
    const int wid = tid >> 5;
    const int l   = tid & 31;

    const int bz = blockIdx.z;
    const long m0 = (long)blockIdx.y * 128;
    const long n0 = (long)blockIdx.x * 128;

    if (aCnt && m0 >= aCnt[bz]) return;
    if (bCnt && n0 >= bCnt[bz]) return;
    const long abase = aOff ? aOff[bz] : 0;
    const long bbase = bOff ? bOff[bz] : 0;
    if (EPI == 0) Cf += (long)bz * sCz;

    const int lr = tid >> 2;
    const int lc = tid & 3;
    const uint32_t srow = (uint32_t)(lr * 80 + lc * 16);
    const __half* gAh = Ah + (abase + m0 + lr) * (long)K + lc * 8;
    const __half* gAl = Al + (abase + m0 + lr) * (long)K + lc * 8;
    const __half* gBh = Bh + (bbase + n0 + lr) * (long)K + lc * 8;
    const __half* gBl = Bl + (bbase + n0 + lr) * (long)K + lc * 8;

    const int warpM = (wid >> 2) * 32;
    const int warpN = (wid & 3) * 32;
    const uint32_t aoff = (uint32_t)((warpM + (l & 15)) * 80 + (l >> 4) * 16);
    const uint32_t boff = (uint32_t)((warpN + (l & 7) + ((l >> 4) << 3)) * 80 +
                                     (((l >> 3) & 1) ? 16 : 0));

    auto load_stage = [&](int stage, int k0) {
        const uint32_t s = sb + (uint32_t)stage * STG_BYTES + srow;
        CP16(s,         gAh + k0);
        CP16(s + 10240, gAl + k0);
        CP16(s + 20480, gBh + k0);
        CP16(s + 30720, gBl + k0);
    };

    float acc[2][4][4];
    uint32_t accx[2][4][2];
#pragma unroll
    for (int i = 0; i < 2; i++)
#pragma unroll
        for (int j = 0; j < 4; j++) {
#pragma unroll
            for (int r = 0; r < 4; r++) acc[i][j][r] = 0.0f;
            accx[i][j][0] = 0u;
            accx[i][j][1] = 0u;
        }

    const int NK = K >> 5;

    load_stage(0, 0);  CP_COMMIT();
    load_stage(1, 32); CP_COMMIT();
    load_stage(2, 64); CP_COMMIT();

    for (int t = 0; t < NK; t++) {
        CP_WAIT2();
        __syncthreads();

        const int tn3 = t + 3;
        if (tn3 < NK) load_stage(tn3 & 3, tn3 * 32);
        CP_COMMIT();

        const uint32_t sbase = sb + (uint32_t)(t & 3) * STG_BYTES;
#pragma unroll
        for (int ks = 0; ks < 2; ks++) {
            uint32_t ah[2][4], al[2][4], bh[2][4], bl[2][4];
#pragma unroll
            for (int mt = 0; mt < 2; mt++)
                LDSM4(ah[mt], sbase + aoff + mt * 1280 + ks * 32);
#pragma unroll
            for (int np = 0; np < 2; np++)
                LDSM4(bh[np], sbase + 20480 + boff + np * 1280 + ks * 32);
#pragma unroll
            for (int mt = 0; mt < 2; mt++)
#pragma unroll
                for (int nt = 0; nt < 4; nt++)
                    MMA16816(acc[mt][nt], ah[mt],
                             bh[nt >> 1][(nt & 1) * 2], bh[nt >> 1][(nt & 1) * 2 + 1]);
#pragma unroll
            for (int mt = 0; mt < 2; mt++)
                LDSM4(al[mt], sbase + 10240 + aoff + mt * 1280 + ks * 32);
#pragma unroll
            for (int np = 0; np < 2; np++)
                LDSM4(bl[np], sbase + 30720 + boff + np * 1280 + ks * 32);
#pragma unroll
            for (int mt = 0; mt < 2; mt++)
#pragma unroll
                for (int nt = 0; nt < 4; nt++)
                    MMA16816F16(accx[mt][nt], ah[mt],
                                bl[nt >> 1][(nt & 1) * 2], bl[nt >> 1][(nt & 1) * 2 + 1]);
#pragma unroll
            for (int mt = 0; mt < 2; mt++)
#pragma unroll
                for (int nt = 0; nt < 4; nt++)
                    MMA16816F16(accx[mt][nt], al[mt],
                                bh[nt >> 1][(nt & 1) * 2], bh[nt >> 1][(nt & 1) * 2 + 1]);
        }
    }

    const int tm = l >> 2;
    const int tn = (l & 3) * 2;
#pragma unroll
    for (int mt = 0; mt < 2; mt++) {
        const long r0 = m0 + warpM + mt * 16 + tm;
        const long r1 = r0 + 8;
#pragma unroll
        for (int nt = 0; nt < 4; nt++) {
            const long col = n0 + warpN + nt * 8 + tn;
            float2 x01 = __half22float2(*(__half2*)&accx[mt][nt][0]);
            float2 x23 = __half22float2(*(__half2*)&accx[mt][nt][1]);
            float c0 = acc[mt][nt][0] + x01.x;
            float c1 = acc[mt][nt][1] + x01.y;
            float c2 = acc[mt][nt][2] + x23.x;
            float c3 = acc[mt][nt][3] + x23.y;
            if (EPI == 0) {
                *(float2*)(Cf + r0 * (long)N + col) = make_float2(c0, c1);
                *(float2*)(Cf + r1 * (long)N + col) = make_float2(c2, c3);
            } else {
                const float b0 = bias[col], b1 = bias[col + 1];
                float v0 = fmaxf(c0 + b0, 0.0f);
                float v1 = fmaxf(c1 + b1, 0.0f);
                float v2 = fmaxf(c2 + b0, 0.0f);
                float v3 = fmaxf(c3 + b1, 0.0f);
                __half h0 = __float2half(v0), h1 = __float2half(v1);
                __half h2 = __float2half(v2), h3 = __float2half(v3);
                __half e0 = __float2half(v0 - __half2float(h0));
                __half e1 = __float2half(v1 - __half2float(h1));
                __half e2 = __float2half(v2 - __half2float(h2));
                __half e3 = __float2half(v3 - __half2float(h3));
                *(__half2*)(Ch + r0 * (long)N + col) = __halves2half2(h0, h1);
                *(__half2*)(Ch + r1 * (long)N + col) = __halves2half2(h2, h3);
                *(__half2*)(Cl + r0 * (long)N + col) = __halves2half2(e0, e1);
                *(__half2*)(Cl + r1 * (long)N + col) = __halves2half2(e2, e3);
            }
        }
    }
}

// ---------------------------------------------------------------------------
// Softmax over compacted cols + scatter to full output (exact vs reference).
// ---------------------------------------------------------------------------
__global__ void __launch_bounds__(256) softmax_scatter_kernel(
    const float* __restrict__ logc,
    const int* __restrict__ qidx, const int* __restrict__ kidx,
    const int* __restrict__ qcnt, const int* __restrict__ kcnt,
    float* __restrict__ out)
{
    const int b = blockIdx.y;
    const int i = blockIdx.x;
    const int tid = threadIdx.x;
    const int qc = qcnt[b];
    const int orow = qidx[b * 1024 + i];
    float* dst = out + ((long)b * 1024 + orow) * 1024;

    if (i >= qc) {
        ((float4*)dst)[tid] = make_float4(0.f, 0.f, 0.f, 0.f);
        return;
    }

    const int kc = kcnt[b];
    const float* src = logc + ((long)b * 1024 + i) * 1024;
    const int j0 = tid * 4;

    __shared__ float row[1024];
    __shared__ float red[8];

    float4 v = ((const float4*)src)[tid];
    float x0 = (j0 + 0 < kc) ? v.x : -1e30f;
    float x1 = (j0 + 1 < kc) ? v.y : -1e30f;
    float x2 = (j0 + 2 < kc) ? v.z : -1e30f;
    float x3 = (j0 + 3 < kc) ? v.w : -1e30f;

    float mx = fmaxf(fmaxf(x0, x1), fmaxf(x2, x3));
#pragma unroll
    for (int o = 16; o > 0; o >>= 1)
        mx = fmaxf(mx, __shfl_xor_sync(0xFFFFFFFFu, mx, o));
    if ((tid & 31) == 0) red[tid >> 5] = mx;
    __syncthreads();
    float bmx = red[0];
#pragma unroll
    for (int w = 1; w < 8; w++) bmx = fmaxf(bmx, red[w]);
    __syncthreads();

    float e0 = expf(x0 - bmx);
    float e1 = expf(x1 - bmx);
    float e2 = expf(x2 - bmx);
    float e3 = expf(x3 - bmx);
    float s = e0 + e1 + e2 + e3;
#pragma unroll
    for (int o = 16; o > 0; o >>= 1)
        s += __shfl_xor_sync(0xFFFFFFFFu, s, o);
    if ((tid & 31) == 0) red[tid >> 5] = s;
    __syncthreads();
    float bs = 0.0f;
#pragma unroll
    for (int w = 0; w < 8; w++) bs += red[w];
    const float inv = 1.0f / bs;

    ((float4*)row)[tid] = make_float4(0.f, 0.f, 0.f, 0.f);
    __syncthreads();
    const int* kix = kidx + b * 1024;
    if (j0 + 0 < kc) row[kix[j0 + 0]] = e0 * inv;
    if (j0 + 1 < kc) row[kix[j0 + 1]] = e1 * inv;
    if (j0 + 2 < kc) row[kix[j0 + 2]] = e2 * inv;
    if (j0 + 3 < kc) row[kix[j0 + 3]] = e3 * inv;
    __syncthreads();

    ((float4*)dst)[tid] = ((float4*)row)[tid];
}

// ---------------------------------------------------------------------------
// kernel_launch
// ---------------------------------------------------------------------------
extern "C" void kernel_launch(void* const* d_in, const int* in_sizes, int n_in,
                              void* d_out, int out_size)
{
    const float* query = (const float*)d_in[0];
    const float* key   = (const float*)d_in[1];
    const int*   qmask = (const int*)  d_in[2];
    const int*   kmask = (const int*)  d_in[3];
    const float* Wq    = (const float*)d_in[4];
    const float* bq    = (const float*)d_in[5];
    const float* Wk    = (const float*)d_in[6];
    const float* bk    = (const float*)d_in[7];
    float* out = (float*)d_out;

    __half *qh, *ql, *kh, *kl, *wqh, *wql, *wkh, *wkl;
    __half *qph, *qpl, *kph, *kpl;
    float* logc;
    int *qidx, *kidx, *qcnt, *kcnt, *qoff, *koff;
    cudaGetSymbolAddress((void**)&qh,   g_qh);
    cudaGetSymbolAddress((void**)&ql,   g_ql);
    cudaGetSymbolAddress((void**)&kh,   g_kh);
    cudaGetSymbolAddress((void**)&kl,   g_kl);
    cudaGetSymbolAddress((void**)&wqh,  g_wqh);
    cudaGetSymbolAddress((void**)&wql,  g_wql);
    cudaGetSymbolAddress((void**)&wkh,  g_wkh);
    cudaGetSymbolAddress((void**)&wkl,  g_wkl);
    cudaGetSymbolAddress((void**)&qph,  g_qph);
    cudaGetSymbolAddress((void**)&qpl,  g_qpl);
    cudaGetSymbolAddress((void**)&kph,  g_kph);
    cudaGetSymbolAddress((void**)&kpl,  g_kpl);
    cudaGetSymbolAddress((void**)&logc, g_logc);
    cudaGetSymbolAddress((void**)&qidx, g_qidx);
    cudaGetSymbolAddress((void**)&kidx, g_kidx);
    cudaGetSymbolAddress((void**)&qcnt, g_qcnt);
    cudaGetSymbolAddress((void**)&kcnt, g_kcnt);
    cudaGetSymbolAddress((void**)&qoff, g_qoff);
    cudaGetSymbolAddress((void**)&koff, g_koff);

    cudaFuncSetAttribute(gemm_fp16x3_kernel<0>,
                         cudaFuncAttributeMaxDynamicSharedMemorySize, SMEM_BYTES);
    cudaFuncSetAttribute(gemm_fp16x3_kernel<1>,
                         cudaFuncAttributeMaxDynamicSharedMemorySize, SMEM_BYTES);

    // Mask partition (ballot scan) + global offsets
    mask_scan_kernel<<<BATCH, 1024>>>(qmask, kmask, qidx, kidx, qcnt, kcnt);
    offsets_kernel<<<1, 32>>>(qcnt, kcnt, qoff, koff);

    // Gather-split: selected rows only, globally compacted (r14 structure)
    dim3 gsg(LQ, BATCH);
    split_gather_kernel<<<gsg, 256>>>(query, qidx, qcnt, qoff, qh, ql);
    split_gather_kernel<<<gsg, 256>>>(key,   kidx, kcnt, koff, kh, kl);
    // Weights
    dim3 gs_w((unsigned)((WN / 4) / 256), 2);
    split_kernel<<<gs_w, 256>>>(Wq, wqh, wql, Wk, wkh, wkl, (int)(WN / 4));

    // Projections over globally-compacted rows (two lean launches)
    dim3 gproj(HID / 128, (BATCH * LQ) / 128, 1);
    gemm_fp16x3_kernel<1><<<gproj, 512, SMEM_BYTES>>>(
        qh, ql, wqh, wql, bq, nullptr, qph, qpl,
        KDIM, HID, 0, nullptr, qoff + BATCH, nullptr, nullptr);
    gemm_fp16x3_kernel<1><<<gproj, 512, SMEM_BYTES>>>(
        kh, kl, wkh, wkl, bk, nullptr, kph, kpl,
        KDIM, HID, 0, nullptr, koff + BATCH, nullptr, nullptr);

    // Batched compacted logits
    dim3 glog(LK / 128, LQ / 128, BATCH);
    gemm_fp16x3_kernel<0><<<glog, 512, SMEM_BYTES>>>(
        qph, qpl, kph, kpl, nullptr, logc, nullptr, nullptr,
        HID, LK, (long)LQ * LK, qoff, qcnt, koff, kcnt);

    // Softmax + scatter
    dim3 gsm(LQ, BATCH);
    softmax_scatter_kernel<<<gsm, 256>>>(logc, qidx, kidx, qcnt, kcnt, out);
}